// round 1
// baseline (speedup 1.0000x reference)
#include <cuda_runtime.h>

// Problem constants
#define Bb 8
#define Ss 2048
#define Dd 512
#define Qq 8
#define Kk 1024
#define Mm (Bb * Ss)   // 16384 tokens

// Scratch (no cudaMalloc allowed)
__device__ float g_residual[Mm * Dd];   // 32 MB
__device__ float g_c2[Qq * Kk];
__device__ int   g_bestidx[Mm];
__device__ float g_loss[Qq];

// ---------------------------------------------------------------------------
// c2[q][k] = ||codebook[q][k]||^2  — one warp per row
// ---------------------------------------------------------------------------
__global__ void c2_kernel(const float* __restrict__ codebooks, float* __restrict__ c2)
{
    int row  = blockIdx.x * 8 + (threadIdx.x >> 5);   // 8 warps/block
    int lane = threadIdx.x & 31;
    const float4* p = (const float4*)(codebooks + (size_t)row * Dd);
    float s = 0.0f;
    #pragma unroll 4
    for (int i = lane; i < Dd / 4; i += 32) {
        float4 v = p[i];
        s += v.x * v.x + v.y * v.y + v.z * v.z + v.w * v.w;
    }
    #pragma unroll
    for (int off = 16; off; off >>= 1) s += __shfl_down_sync(0xffffffffu, s, off);
    if (lane == 0) c2[row] = s;
}

// ---------------------------------------------------------------------------
// Fused GEMM + argmin:
// for each token m in [m0, m0+128): argmin_k ( c2[k] - 2 * dot(R[m], C[k]) )
// Block: 256 threads, 128x128 tile, 8x8 micro-tile per thread, k-tile = 16.
// ---------------------------------------------------------------------------
__global__ __launch_bounds__(256, 1)
void argmin_kernel(const float* __restrict__ R,
                   const float* __restrict__ C,
                   const float* __restrict__ c2,
                   int* __restrict__ bestidx)
{
    __shared__ float As[128][20];   // padded: row stride 80B (16B-aligned)
    __shared__ float Bs[128][20];
    __shared__ float s_bestval[128];
    __shared__ int   s_bestidx[128];

    const int tid = threadIdx.x;
    const int tx  = tid & 15;       // code-dim thread coord
    const int ty  = tid >> 4;       // token-dim thread coord
    const int m0  = blockIdx.x * 128;

    if (tid < 128) { s_bestval[tid] = 3.4e38f; s_bestidx[tid] = 0; }

    // global->smem tile loader mapping: 512 float4 per tile / 256 threads = 2 each
    const int u0 = tid, u1 = tid + 256;
    const int ar0 = u0 >> 2, as0 = (u0 & 3) * 4;
    const int ar1 = u1 >> 2, as1 = (u1 & 3) * 4;

    // smem reuse for cross-thread argmin reduction (post-compute)
    float* vals_red = &As[0][0];          // 128*16 floats
    int*   idx_red  = (int*)&Bs[0][0];    // 128*16 ints

    for (int nt = 0; nt < Kk / 128; ++nt) {
        const int n0 = nt * 128;

        float acc[8][8];
        #pragma unroll
        for (int i = 0; i < 8; ++i)
            #pragma unroll
            for (int j = 0; j < 8; ++j) acc[i][j] = 0.0f;

        // prefetch k-tile 0 into registers
        float4 a0 = *(const float4*)&R[(size_t)(m0 + ar0) * Dd + as0];
        float4 a1 = *(const float4*)&R[(size_t)(m0 + ar1) * Dd + as1];
        float4 b0 = *(const float4*)&C[(size_t)(n0 + ar0) * Dd + as0];
        float4 b1 = *(const float4*)&C[(size_t)(n0 + ar1) * Dd + as1];

        for (int kt = 0; kt < Dd / 16; ++kt) {
            __syncthreads();   // previous compute / reduction readers done
            *(float4*)&As[ar0][as0] = a0;
            *(float4*)&As[ar1][as1] = a1;
            *(float4*)&Bs[ar0][as0] = b0;
            *(float4*)&Bs[ar1][as1] = b1;
            __syncthreads();

            if (kt + 1 < Dd / 16) {
                const int k0 = (kt + 1) * 16;
                a0 = *(const float4*)&R[(size_t)(m0 + ar0) * Dd + k0 + as0];
                a1 = *(const float4*)&R[(size_t)(m0 + ar1) * Dd + k0 + as1];
                b0 = *(const float4*)&C[(size_t)(n0 + ar0) * Dd + k0 + as0];
                b1 = *(const float4*)&C[(size_t)(n0 + ar1) * Dd + k0 + as1];
            }

            #pragma unroll
            for (int k = 0; k < 16; ++k) {
                float a[8], b[8];
                #pragma unroll
                for (int i = 0; i < 8; ++i) a[i] = As[ty + 16 * i][k];
                #pragma unroll
                for (int j = 0; j < 8; ++j) b[j] = Bs[tx + 16 * j][k];
                #pragma unroll
                for (int i = 0; i < 8; ++i)
                    #pragma unroll
                    for (int j = 0; j < 8; ++j)
                        acc[i][j] = fmaf(a[i], b[j], acc[i][j]);
            }
        }
        __syncthreads();   // all compute done before smem is reused for reduction

        // distances + per-thread argmin over this thread's 8 codes per token row
        float c2v[8];
        #pragma unroll
        for (int j = 0; j < 8; ++j) c2v[j] = __ldg(&c2[n0 + tx + 16 * j]);

        #pragma unroll
        for (int i = 0; i < 8; ++i) {
            float bv = 3.4e38f; int bi = 0x7fffffff;
            #pragma unroll
            for (int j = 0; j < 8; ++j) {
                float d = fmaf(-2.0f, acc[i][j], c2v[j]);
                int   n = n0 + tx + 16 * j;
                if (d < bv || (d == bv && n < bi)) { bv = d; bi = n; }
            }
            vals_red[(ty + 16 * i) * 16 + tx] = bv;
            idx_red [(ty + 16 * i) * 16 + tx] = bi;
        }
        __syncthreads();

        if (tid < 128) {
            float bv = s_bestval[tid]; int bi = s_bestidx[tid];
            #pragma unroll
            for (int t = 0; t < 16; ++t) {
                float v  = vals_red[tid * 16 + t];
                int   ix = idx_red [tid * 16 + t];
                if (v < bv || (v == bv && ix < bi)) { bv = v; bi = ix; }
            }
            s_bestval[tid] = bv; s_bestidx[tid] = bi;
        }
        __syncthreads();
    }

    if (tid < 128) bestidx[m0 + tid] = s_bestidx[tid];
}

// ---------------------------------------------------------------------------
// Per-token update: residual -= code, out_q += code, loss += ||new_r||^2,
// write index (as float). One block (128 threads) per token; float4 lanes.
// ---------------------------------------------------------------------------
__global__ __launch_bounds__(128)
void update_kernel(const float* __restrict__ C,
                   const int* __restrict__ bestidx,
                   float* __restrict__ residual,
                   float* __restrict__ outq,
                   float* __restrict__ out_idx,
                   float* __restrict__ loss,
                   int qstage)
{
    const int token = blockIdx.x;
    const int t = threadIdx.x;   // 128 threads, Dd/4 = 128 float4s
    const int idx = bestidx[token];

    const float4* c = (const float4*)(C + (size_t)idx * Dd);
    float4* r = (float4*)(residual + (size_t)token * Dd);
    float4* o = (float4*)(outq + (size_t)token * Dd);

    float4 cv = c[t];
    float4 rv = r[t];
    float4 ov = o[t];
    float4 nr = make_float4(rv.x - cv.x, rv.y - cv.y, rv.z - cv.z, rv.w - cv.w);
    r[t] = nr;
    o[t] = make_float4(ov.x + cv.x, ov.y + cv.y, ov.z + cv.z, ov.w + cv.w);

    float ls = nr.x * nr.x + nr.y * nr.y + nr.z * nr.z + nr.w * nr.w;
    #pragma unroll
    for (int off = 16; off; off >>= 1) ls += __shfl_down_sync(0xffffffffu, ls, off);

    __shared__ float ws[4];
    if ((t & 31) == 0) ws[t >> 5] = ls;
    __syncthreads();
    if (t == 0) {
        atomicAdd(loss, ws[0] + ws[1] + ws[2] + ws[3]);
        out_idx[(size_t)token * Qq + qstage] = (float)idx;
    }
}

// ---------------------------------------------------------------------------
// Tail outputs: all_expired (zeros) then all_losses (mean over B*S*D)
// ---------------------------------------------------------------------------
__global__ void finalize_kernel(float* __restrict__ out, const float* __restrict__ loss)
{
    const size_t base = (size_t)Mm * Dd + (size_t)Mm * Qq;
    int t = threadIdx.x;
    if (t < Qq)
        out[base + t] = 0.0f;
    else if (t < 2 * Qq)
        out[base + Qq + (t - Qq)] = loss[t - Qq] * (1.0f / ((float)Mm * (float)Dd));
}

// ---------------------------------------------------------------------------
extern "C" void kernel_launch(void* const* d_in, const int* in_sizes, int n_in,
                              void* d_out, int out_size)
{
    const float* x  = (const float*)d_in[0];   // [B,S,D] f32
    const float* cb = (const float*)d_in[1];   // [Q,K,D] f32
    float* out = (float*)d_out;

    float* residual; cudaGetSymbolAddress((void**)&residual, g_residual);
    float* c2;       cudaGetSymbolAddress((void**)&c2,       g_c2);
    int*   bidx;     cudaGetSymbolAddress((void**)&bidx,     g_bestidx);
    float* loss;     cudaGetSymbolAddress((void**)&loss,     g_loss);

    cudaMemcpyAsync(residual, x, (size_t)Mm * Dd * sizeof(float),
                    cudaMemcpyDeviceToDevice);
    cudaMemsetAsync(out, 0, (size_t)Mm * Dd * sizeof(float));   // quantized accum
    cudaMemsetAsync(loss, 0, Qq * sizeof(float));

    c2_kernel<<<Qq * Kk / 8, 256>>>(cb, c2);

    for (int q = 0; q < Qq; ++q) {
        const float* Cq = cb + (size_t)q * Kk * Dd;
        argmin_kernel<<<Mm / 128, 256>>>(residual, Cq, c2 + q * Kk, bidx);
        update_kernel<<<Mm, 128>>>(Cq, bidx, residual, out,
                                   out + (size_t)Mm * Dd, loss + q, q);
    }

    finalize_kernel<<<1, 2 * Qq>>>(out, loss);
}

// round 3
// speedup vs baseline: 5.0006x; 5.0006x over previous
#include <cuda_runtime.h>
#include <cuda_bf16.h>
#include <cstdint>

// Problem constants
#define Bb 8
#define Ss 2048
#define Dd 512
#define Qq 8
#define Kk 1024
#define Mm (Bb * Ss)   // 16384 tokens

// Scratch (no cudaMalloc allowed)
__device__ float          g_residual[Mm * Dd];   // 32 MB fp32 residual
__device__ __nv_bfloat16  g_res16[Mm * Dd];      // 16 MB bf16 residual
__device__ __nv_bfloat16  g_cb16[Qq * Kk * Dd];  //  8 MB bf16 codebooks
__device__ float          g_dist[Mm * Kk];       // 64 MB approx distances
__device__ float          g_c2[Qq * Kk];
__device__ int            g_bestidx[Mm];
__device__ float          g_loss[Qq];

// ---------------------------------------------------------------------------
// helpers
// ---------------------------------------------------------------------------
__device__ __forceinline__ uint32_t smem_u32(const void* p) {
    uint32_t a;
    asm("{ .reg .u64 t; cvta.to.shared.u64 t, %1; cvt.u32.u64 %0, t; }"
        : "=r"(a) : "l"(p));
    return a;
}
__device__ __forceinline__ void cp16(uint32_t sa, const void* g) {
    asm volatile("cp.async.cg.shared.global [%0], [%1], 16;"
                 :: "r"(sa), "l"(g) : "memory");
}
__device__ __forceinline__ void cp_commit() {
    asm volatile("cp.async.commit_group;" ::: "memory");
}
__device__ __forceinline__ void cp_wait1() {
    asm volatile("cp.async.wait_group 1;" ::: "memory");
}
__device__ __forceinline__ void cp_wait0() {
    asm volatile("cp.async.wait_group 0;" ::: "memory");
}
__device__ __forceinline__ void ldsm4(uint32_t* r, uint32_t addr) {
    asm volatile("ldmatrix.sync.aligned.m8n8.x4.shared.b16 {%0,%1,%2,%3}, [%4];"
                 : "=r"(r[0]), "=r"(r[1]), "=r"(r[2]), "=r"(r[3])
                 : "r"(addr));
}
__device__ __forceinline__ void mma_bf16(float* c, const uint32_t* a,
                                         uint32_t b0, uint32_t b1) {
    asm volatile(
        "mma.sync.aligned.m16n8k16.row.col.f32.bf16.bf16.f32 "
        "{%0,%1,%2,%3}, {%4,%5,%6,%7}, {%8,%9}, {%0,%1,%2,%3};"
        : "+f"(c[0]), "+f"(c[1]), "+f"(c[2]), "+f"(c[3])
        : "r"(a[0]), "r"(a[1]), "r"(a[2]), "r"(a[3]), "r"(b0), "r"(b1));
}

// ---------------------------------------------------------------------------
// fp32 -> bf16 bulk convert (float4 -> 2x bf162 per thread)
// ---------------------------------------------------------------------------
__global__ void conv_kernel(const float4* __restrict__ in,
                            __nv_bfloat162* __restrict__ out, int n4)
{
    int i = blockIdx.x * 256 + threadIdx.x;
    if (i < n4) {
        float4 v = in[i];
        out[2 * i]     = __floats2bfloat162_rn(v.x, v.y);
        out[2 * i + 1] = __floats2bfloat162_rn(v.z, v.w);
    }
}

// ---------------------------------------------------------------------------
// c2[q][k] = ||codebook[q][k]||^2  — one warp per row (fp32 exact)
// ---------------------------------------------------------------------------
__global__ void c2_kernel(const float* __restrict__ codebooks, float* __restrict__ c2)
{
    int row  = blockIdx.x * 8 + (threadIdx.x >> 5);
    int lane = threadIdx.x & 31;
    const float4* p = (const float4*)(codebooks + (size_t)row * Dd);
    float s = 0.0f;
    #pragma unroll 4
    for (int i = lane; i < Dd / 4; i += 32) {
        float4 v = p[i];
        s += v.x * v.x + v.y * v.y + v.z * v.z + v.w * v.w;
    }
    #pragma unroll
    for (int off = 16; off; off >>= 1) s += __shfl_down_sync(0xffffffffu, s, off);
    if (lane == 0) c2[row] = s;
}

// ---------------------------------------------------------------------------
// bf16 mma.sync GEMM -> approx distances.
// CTA 128x128, BK=64 bf16 (128B rows, SW128 xor-swizzle), double-buffered
// cp.async, 8 warps of 32x64 (mma m16n8k16 grid 2x8).
// dist[m][n] = c2[n] - 2 * dot(bf16(r_m), bf16(c_n))
// ---------------------------------------------------------------------------
#define GEMM_SMEM 65536   // 2 bufs * (A 16KB + B 16KB)

__global__ __launch_bounds__(256, 2)
void gemm_dist_kernel(const __nv_bfloat16* __restrict__ A16,
                      const __nv_bfloat16* __restrict__ B16,
                      const float* __restrict__ c2,
                      float* __restrict__ dist)
{
    extern __shared__ char sm[];
    const uint32_t smb   = smem_u32(sm);
    const uint32_t Abase = smb;           // [2][16384]
    const uint32_t Bbase = smb + 32768;   // [2][16384]

    const int tid  = threadIdx.x;
    const int lane = tid & 31;
    const int warp = tid >> 5;
    const int bm = blockIdx.x * 128;
    const int bn = blockIdx.y * 128;
    const int wm = (warp & 3) * 32;
    const int wn = (warp >> 2) * 64;

    const char* gA = (const char*)(A16 + (size_t)bm * Dd);
    const char* gB = (const char*)(B16 + (size_t)bn * Dd);

    float acc[2][8][4];
    #pragma unroll
    for (int mi = 0; mi < 2; ++mi)
        #pragma unroll
        for (int ni = 0; ni < 8; ++ni)
            #pragma unroll
            for (int j = 0; j < 4; ++j) acc[mi][ni][j] = 0.0f;

    // loader mapping: per tile 128 rows x 8 chunks(16B); 4 chunks/thread each for A,B
    #define LOAD_TILE(kt, buf)                                                  \
        {                                                                       \
            _Pragma("unroll")                                                   \
            for (int i = 0; i < 4; ++i) {                                       \
                int u = tid + 256 * i;                                          \
                int row = u >> 3, ch = u & 7;                                   \
                uint32_t so = (uint32_t)(row * 128 + ((ch ^ (row & 7)) * 16));  \
                size_t go = (size_t)row * (Dd * 2) + (kt) * 128 + ch * 16;      \
                cp16(Abase + (buf) * 16384 + so, gA + go);                      \
                cp16(Bbase + (buf) * 16384 + so, gB + go);                      \
            }                                                                   \
            cp_commit();                                                        \
        }

    LOAD_TILE(0, 0);

    for (int kt = 0; kt < 8; ++kt) {
        const int buf = kt & 1;
        if (kt < 7) { LOAD_TILE(kt + 1, buf ^ 1); cp_wait1(); }
        else        { cp_wait0(); }
        __syncthreads();

        #pragma unroll
        for (int s = 0; s < 4; ++s) {
            uint32_t a[2][4], b[4][4];
            const int ch = s * 2 + (lane >> 4);
            #pragma unroll
            for (int mi = 0; mi < 2; ++mi) {
                int row = wm + mi * 16 + (lane & 15);
                ldsm4(a[mi], Abase + buf * 16384 + row * 128 + ((ch ^ (row & 7)) * 16));
            }
            #pragma unroll
            for (int nj = 0; nj < 4; ++nj) {
                int row = wn + nj * 16 + (lane & 15);
                ldsm4(b[nj], Bbase + buf * 16384 + row * 128 + ((ch ^ (row & 7)) * 16));
            }
            #pragma unroll
            for (int mi = 0; mi < 2; ++mi)
                #pragma unroll
                for (int ni = 0; ni < 8; ++ni)
                    mma_bf16(acc[mi][ni], a[mi],
                             b[ni >> 1][ni & 1], b[ni >> 1][(ni & 1) + 2]);
        }
        __syncthreads();
    }

    // epilogue: d = c2[n] - 2*acc, float2 stores
    const int g = lane >> 2, t4 = lane & 3;
    #pragma unroll
    for (int mi = 0; mi < 2; ++mi) {
        const int m0 = bm + wm + mi * 16 + g;
        #pragma unroll
        for (int ni = 0; ni < 8; ++ni) {
            const int n = bn + wn + ni * 8 + 2 * t4;
            float2 cc = *(const float2*)(c2 + n);
            float2 d0, d1;
            d0.x = fmaf(-2.0f, acc[mi][ni][0], cc.x);
            d0.y = fmaf(-2.0f, acc[mi][ni][1], cc.y);
            d1.x = fmaf(-2.0f, acc[mi][ni][2], cc.x);
            d1.y = fmaf(-2.0f, acc[mi][ni][3], cc.y);
            *(float2*)(dist + (size_t)m0 * Kk + n)       = d0;
            *(float2*)(dist + (size_t)(m0 + 8) * Kk + n) = d1;
        }
    }
}

// ---------------------------------------------------------------------------
// Refine: warp per token. Scan 1024 approx distances, exact-rescore all
// candidates within MARGIN of the min (fp32, warp-cooperative dot),
// first-index tie-break. MARGIN=12 rigorously covers 2*bf16 error bound.
// ---------------------------------------------------------------------------
__global__ __launch_bounds__(256)
void refine_kernel(const float* __restrict__ dist,
                   const float* __restrict__ R,
                   const float* __restrict__ C,
                   const float* __restrict__ c2,
                   int* __restrict__ bestidx)
{
    const int warp = threadIdx.x >> 5, lane = threadIdx.x & 31;
    const int token = blockIdx.x * 8 + warp;

    const float4* dp = (const float4*)(dist + (size_t)token * Kk);
    float v[32];
    float vmin = 3.4e38f;
    #pragma unroll
    for (int i = 0; i < 8; ++i) {
        float4 f = dp[lane + 32 * i];
        v[4 * i] = f.x; v[4 * i + 1] = f.y; v[4 * i + 2] = f.z; v[4 * i + 3] = f.w;
        vmin = fminf(vmin, fminf(fminf(f.x, f.y), fminf(f.z, f.w)));
    }
    #pragma unroll
    for (int o = 16; o; o >>= 1) vmin = fminf(vmin, __shfl_xor_sync(~0u, vmin, o));

    const float thresh = vmin + 12.0f;
    unsigned mask = 0;
    #pragma unroll
    for (int s = 0; s < 32; ++s)
        if (v[s] <= thresh) mask |= 1u << s;

    float bd = 3.4e38f;
    int   bn_ = 1 << 30;
    const float4* rr = (const float4*)(R + (size_t)token * Dd);

    while (true) {
        unsigned has = __ballot_sync(~0u, mask != 0);
        if (!has) break;
        int leader = __ffs(has) - 1;
        int s = 0;
        if (lane == leader) { s = __ffs(mask) - 1; mask &= mask - 1; }
        s = __shfl_sync(~0u, s, leader);
        const int n = 128 * (s >> 2) + 4 * leader + (s & 3);

        const float4* cc4 = (const float4*)(C + (size_t)n * Dd);
        float ssum = 0.0f;
        #pragma unroll
        for (int t = 0; t < 4; ++t) {
            float4 a = rr[lane + 32 * t];
            float4 b = cc4[lane + 32 * t];
            ssum += a.x * b.x + a.y * b.y + a.z * b.z + a.w * b.w;
        }
        #pragma unroll
        for (int o = 16; o; o >>= 1) ssum += __shfl_xor_sync(~0u, ssum, o);

        float d = fmaf(-2.0f, ssum, __ldg(c2 + n));
        if (d < bd || (d == bd && n < bn_)) { bd = d; bn_ = n; }
    }
    if (lane == 0) bestidx[token] = bn_;
}

// ---------------------------------------------------------------------------
// Per-token update: residual -= code (fp32 + bf16 shadow), out_q += code,
// loss += ||new_r||^2, write index.
// ---------------------------------------------------------------------------
__global__ __launch_bounds__(128)
void update_kernel(const float* __restrict__ C,
                   const int* __restrict__ bestidx,
                   float* __restrict__ residual,
                   __nv_bfloat16* __restrict__ res16,
                   float* __restrict__ outq,
                   float* __restrict__ out_idx,
                   float* __restrict__ loss,
                   int qstage)
{
    const int token = blockIdx.x;
    const int t = threadIdx.x;
    const int idx = bestidx[token];

    const float4* c = (const float4*)(C + (size_t)idx * Dd);
    float4* r = (float4*)(residual + (size_t)token * Dd);
    float4* o = (float4*)(outq + (size_t)token * Dd);
    __nv_bfloat162* r16 = (__nv_bfloat162*)(res16 + (size_t)token * Dd);

    float4 cv = c[t];
    float4 rv = r[t];
    float4 ov = o[t];
    float4 nr = make_float4(rv.x - cv.x, rv.y - cv.y, rv.z - cv.z, rv.w - cv.w);
    r[t] = nr;
    r16[2 * t]     = __floats2bfloat162_rn(nr.x, nr.y);
    r16[2 * t + 1] = __floats2bfloat162_rn(nr.z, nr.w);
    o[t] = make_float4(ov.x + cv.x, ov.y + cv.y, ov.z + cv.z, ov.w + cv.w);

    float ls = nr.x * nr.x + nr.y * nr.y + nr.z * nr.z + nr.w * nr.w;
    #pragma unroll
    for (int off = 16; off; off >>= 1) ls += __shfl_down_sync(0xffffffffu, ls, off);

    __shared__ float ws[4];
    if ((t & 31) == 0) ws[t >> 5] = ls;
    __syncthreads();
    if (t == 0) {
        atomicAdd(loss, ws[0] + ws[1] + ws[2] + ws[3]);
        out_idx[(size_t)token * Qq + qstage] = (float)idx;
    }
}

// ---------------------------------------------------------------------------
// Tail outputs: all_expired (zeros) then all_losses (mean over B*S*D)
// ---------------------------------------------------------------------------
__global__ void finalize_kernel(float* __restrict__ out, const float* __restrict__ loss)
{
    const size_t base = (size_t)Mm * Dd + (size_t)Mm * Qq;
    int t = threadIdx.x;
    if (t < Qq)
        out[base + t] = 0.0f;
    else if (t < 2 * Qq)
        out[base + Qq + (t - Qq)] = loss[t - Qq] * (1.0f / ((float)Mm * (float)Dd));
}

// ---------------------------------------------------------------------------
extern "C" void kernel_launch(void* const* d_in, const int* in_sizes, int n_in,
                              void* d_out, int out_size)
{
    const float* x  = (const float*)d_in[0];   // [B,S,D] f32
    const float* cb = (const float*)d_in[1];   // [Q,K,D] f32
    float* out = (float*)d_out;

    float* residual;         cudaGetSymbolAddress((void**)&residual, g_residual);
    __nv_bfloat16* res16;    cudaGetSymbolAddress((void**)&res16,    g_res16);
    __nv_bfloat16* cb16;     cudaGetSymbolAddress((void**)&cb16,     g_cb16);
    float* dist;             cudaGetSymbolAddress((void**)&dist,     g_dist);
    float* c2;               cudaGetSymbolAddress((void**)&c2,       g_c2);
    int*   bidx;             cudaGetSymbolAddress((void**)&bidx,     g_bestidx);
    float* loss;             cudaGetSymbolAddress((void**)&loss,     g_loss);

    cudaFuncSetAttribute(gemm_dist_kernel,
                         cudaFuncAttributeMaxDynamicSharedMemorySize, GEMM_SMEM);

    cudaMemcpyAsync(residual, x, (size_t)Mm * Dd * sizeof(float),
                    cudaMemcpyDeviceToDevice);
    cudaMemsetAsync(out, 0, (size_t)Mm * Dd * sizeof(float));
    cudaMemsetAsync(loss, 0, Qq * sizeof(float));

    conv_kernel<<<(Mm * Dd / 4 + 255) / 256, 256>>>((const float4*)x,
                                                    (__nv_bfloat162*)res16,
                                                    Mm * Dd / 4);
    conv_kernel<<<(Qq * Kk * Dd / 4 + 255) / 256, 256>>>((const float4*)cb,
                                                         (__nv_bfloat162*)cb16,
                                                         Qq * Kk * Dd / 4);
    c2_kernel<<<Qq * Kk / 8, 256>>>(cb, c2);

    for (int q = 0; q < Qq; ++q) {
        const float* Cq = cb + (size_t)q * Kk * Dd;
        const __nv_bfloat16* Cq16 = cb16 + (size_t)q * Kk * Dd;
        dim3 grid(Mm / 128, Kk / 128);
        gemm_dist_kernel<<<grid, 256, GEMM_SMEM>>>(res16, Cq16, c2 + q * Kk, dist);
        refine_kernel<<<Mm / 8, 256>>>(dist, residual, Cq, c2 + q * Kk, bidx);
        update_kernel<<<Mm, 128>>>(Cq, bidx, residual, res16, out,
                                   out + (size_t)Mm * Dd, loss + q, q);
    }

    finalize_kernel<<<1, 2 * Qq>>>(out, loss);
}